// round 3
// baseline (speedup 1.0000x reference)
#include <cuda_runtime.h>

// ---------------- problem constants (fixed shapes) ----------------
#define C_CLASSES   12
#define LOG_DHW     20                    // d*h*w = 64*128*128 = 2^20
#define DHW         (1u << LOG_DHW)
#define NPIX        (2u * DHW)            // 2,097,152
#define MIN_KEPT_K  10000u
#define IGNORE_LBL  255
#define INF_BITS    0x7F800000u
#define B09_BITS    0x3F666666u           // bits of 0.9f (probs >= 0, uint order == float order)

// ---------------- device scratch ----------------
__device__ unsigned int g_prob_bits[NPIX];   // prob-at-label as monotone uint bits; INF for invalid
__device__ unsigned int g_buf[NPIX];         // compacted elements of L0 bin b0
__device__ unsigned int g_hist[1024];        // L0 histogram of bits>>21
__device__ unsigned int g_state[4];          // [0]=b0 [1]=rank-in-b0 [2]=keep_all
__device__ unsigned int g_bufcnt;
__device__ double       g_sumAll, g_sumB, g_sumL;
__device__ unsigned int g_cntAll, g_cntB, g_cntL;

// ---------------- zero scratch ----------------
__global__ void zero_kernel() {
    int t = threadIdx.x;
    if (t < 1024) g_hist[t] = 0u;
    if (t < 4)    g_state[t] = 0u;
    if (t == 0) {
        g_bufcnt = 0u;
        g_sumAll = 0.0; g_sumB = 0.0; g_sumL = 0.0;
        g_cntAll = 0u;  g_cntB = 0u;  g_cntL = 0u;
    }
}

// ---------------- per-pixel CE -> prob bits ----------------
__device__ __forceinline__ unsigned int pixel_prob_bits(const float v[C_CLASSES], int l) {
    float m = v[0];
#pragma unroll
    for (int c = 1; c < C_CLASSES; c++) m = fmaxf(m, v[c]);
    float sum = 0.f, xl = 0.f;
#pragma unroll
    for (int c = 0; c < C_CLASSES; c++) {
        sum += __expf(v[c] - m);
        if (c == l) xl = v[c];
    }
    float lp = xl - (m + __logf(sum));
    if (l == IGNORE_LBL) return INF_BITS;           // invalid -> +inf (sorts last, like reference)
    return __float_as_uint(__expf(lp));             // prob in [0,1]
}

// ---------------- pass 1: compute prob bits + L0 histogram ----------------
#define CB_BLOCKS  1024
#define CB_THREADS 256

__global__ void __launch_bounds__(CB_THREADS)
compute_kernel(const float* __restrict__ pred, const int* __restrict__ tgt) {
    __shared__ unsigned int sh[1024];
    for (int i = threadIdx.x; i < 1024; i += CB_THREADS) sh[i] = 0u;
    __syncthreads();

    const unsigned stride_px = CB_BLOCKS * CB_THREADS * 4u;
    for (unsigned p = (blockIdx.x * CB_THREADS + threadIdx.x) * 4u; p < NPIX; p += stride_px) {
        unsigned n = p >> LOG_DHW;
        unsigned s = p & (DHW - 1u);
        const float* base = pred + (((size_t)n * C_CLASSES) << LOG_DHW) + s;

        float4 x[C_CLASSES];
#pragma unroll
        for (int c = 0; c < C_CLASSES; c++)
            x[c] = __ldcs((const float4*)(base + ((size_t)c << LOG_DHW)));

        int4 lab = __ldcs((const int4*)tgt + (p >> 2));   // target is int32 (jax x64 disabled)

        float v[C_CLASSES];
        uint4 pb;
#pragma unroll
        for (int c = 0; c < C_CLASSES; c++) v[c] = x[c].x;
        pb.x = pixel_prob_bits(v, lab.x);
#pragma unroll
        for (int c = 0; c < C_CLASSES; c++) v[c] = x[c].y;
        pb.y = pixel_prob_bits(v, lab.y);
#pragma unroll
        for (int c = 0; c < C_CLASSES; c++) v[c] = x[c].z;
        pb.z = pixel_prob_bits(v, lab.z);
#pragma unroll
        for (int c = 0; c < C_CLASSES; c++) v[c] = x[c].w;
        pb.w = pixel_prob_bits(v, lab.w);

        ((uint4*)g_prob_bits)[p >> 2] = pb;

        atomicAdd(&sh[pb.x >> 21], 1u);
        atomicAdd(&sh[pb.y >> 21], 1u);
        atomicAdd(&sh[pb.z >> 21], 1u);
        atomicAdd(&sh[pb.w >> 21], 1u);
    }
    __syncthreads();
    for (int i = threadIdx.x; i < 1024; i += CB_THREADS) {
        unsigned c = sh[i];
        if (c) atomicAdd(&g_hist[i], c);
    }
}

// ---------------- selA: locate kth element's L0 bin ----------------
__global__ void __launch_bounds__(1024) selA_kernel() {
    __shared__ unsigned int scanS[1024];
    __shared__ unsigned int resB, resR;
    const int t = threadIdx.x;
    unsigned inv       = g_hist[1020];                 // INF_BITS>>21 = 1020; valid probs <= bin 508
    unsigned num_valid = NPIX - inv;
    unsigned keep_all  = (MIN_KEPT_K >= num_valid) ? 1u : 0u;
    unsigned mk        = (MIN_KEPT_K < num_valid) ? MIN_KEPT_K : num_valid;
    unsigned k         = (mk > 0u) ? (mk - 1u) : 0u;

    if (t == 0) { resB = 0u; resR = 0u; }
    unsigned local = g_hist[t];
    scanS[t] = local;
    __syncthreads();
    for (int off = 1; off < 1024; off <<= 1) {
        unsigned add = (t >= off) ? scanS[t - off] : 0u;
        __syncthreads();
        scanS[t] += add;
        __syncthreads();
    }
    unsigned incl = scanS[t], excl = incl - local;
    if (k >= excl && k < incl) { resB = (unsigned)t; resR = k - excl; }
    __syncthreads();
    if (t == 0) {
        g_state[0] = resB;
        g_state[1] = resR;
        g_state[2] = keep_all;
    }
}

// ---------------- pass 2: fused partial sums + boundary-bin compaction ----------------
#define P2_BLOCKS  512
#define P2_THREADS 256
// 512 blocks * 4 iters * 256 threads = 524288 uint4 = NPIX elements exactly

__global__ void __launch_bounds__(P2_THREADS) pass2_kernel() {
    const unsigned b0 = g_state[0];
    float    sAll = 0.f, sB = 0.f, sL = 0.f;
    unsigned cAll = 0u,  cB = 0u,  cL = 0u;

    unsigned base = blockIdx.x * (P2_THREADS * 4u);
#pragma unroll
    for (int i = 0; i < 4; i++) {
        uint4 pb = ((const uint4*)g_prob_bits)[base + i * P2_THREADS + threadIdx.x];
        unsigned bs[4] = { pb.x, pb.y, pb.z, pb.w };
#pragma unroll
        for (int j = 0; j < 4; j++) {
            unsigned b = bs[j];
            if (b != INF_BITS) {
                float nll = -__logf(__uint_as_float(b));
                cAll++; sAll += nll;
                if (b <= B09_BITS) { cB++; sB += nll; }
                unsigned bin = b >> 21;
                if (bin < b0)       { cL++; sL += nll; }
                else if (bin == b0) { g_buf[atomicAdd(&g_bufcnt, 1u)] = b; }
            }
        }
    }

    // block reduction of 3 float + 3 uint accumulators
#pragma unroll
    for (int off = 16; off > 0; off >>= 1) {
        sAll += __shfl_down_sync(0xFFFFFFFFu, sAll, off);
        sB   += __shfl_down_sync(0xFFFFFFFFu, sB,   off);
        sL   += __shfl_down_sync(0xFFFFFFFFu, sL,   off);
        cAll += __shfl_down_sync(0xFFFFFFFFu, cAll, off);
        cB   += __shfl_down_sync(0xFFFFFFFFu, cB,   off);
        cL   += __shfl_down_sync(0xFFFFFFFFu, cL,   off);
    }
    __shared__ float    wsA[8], wsB[8], wsL[8];
    __shared__ unsigned wcA[8], wcB[8], wcL[8];
    int w = threadIdx.x >> 5;
    if ((threadIdx.x & 31) == 0) {
        wsA[w] = sAll; wsB[w] = sB; wsL[w] = sL;
        wcA[w] = cAll; wcB[w] = cB; wcL[w] = cL;
    }
    __syncthreads();
    if (threadIdx.x == 0) {
        float    SA = 0.f, SB = 0.f, SL = 0.f;
        unsigned CA = 0u,  CBc = 0u, CL = 0u;
#pragma unroll
        for (int i = 0; i < 8; i++) {
            SA += wsA[i]; SB += wsB[i]; SL += wsL[i];
            CA += wcA[i]; CBc += wcB[i]; CL += wcL[i];
        }
        atomicAdd(&g_sumAll, (double)SA);
        atomicAdd(&g_sumB,   (double)SB);
        atomicAdd(&g_sumL,   (double)SL);
        atomicAdd(&g_cntAll, CA);
        atomicAdd(&g_cntB,   CBc);
        atomicAdd(&g_cntL,   CL);
    }
}

// ---------------- finalize: exact kth bits via in-shared radix + final loss ----------------
__global__ void __launch_bounds__(1024) finalize_kernel(float* __restrict__ out) {
    __shared__ unsigned cntS[2048];
    __shared__ float    sumS[2048];
    __shared__ unsigned scanS[1024];
    __shared__ unsigned resBin, resRank;
    __shared__ float    accS;
    __shared__ unsigned accC;
    const int t = threadIdx.x;

    const unsigned keep_all = g_state[2];
    const unsigned b0 = g_state[0];
    const unsigned r  = g_state[1];
    const unsigned M  = g_bufcnt;

    // ---- round 1: histogram of mid 11 bits over boundary-bin elements ----
    cntS[t] = 0u; cntS[t + 1024] = 0u;
    sumS[t] = 0.f; sumS[t + 1024] = 0.f;
    if (t == 0) { resBin = 0u; resRank = 0u; accS = 0.f; accC = 0u; }
    __syncthreads();
    for (unsigned i = t; i < M; i += 1024) {
        unsigned b = g_buf[i];
        unsigned mid = (b >> 10) & 0x7FFu;
        atomicAdd(&cntS[mid], 1u);
        atomicAdd(&sumS[mid], -__logf(__uint_as_float(b)));
    }
    __syncthreads();
    unsigned c0 = cntS[2 * t], c1 = cntS[2 * t + 1];
    unsigned local = c0 + c1;
    scanS[t] = local;
    __syncthreads();
    for (int off = 1; off < 1024; off <<= 1) {
        unsigned add = (t >= off) ? scanS[t - off] : 0u;
        __syncthreads();
        scanS[t] += add;
        __syncthreads();
    }
    unsigned incl = scanS[t], excl = incl - local;
    if (r >= excl && r < incl) {
        if (r < excl + c0) { resBin = 2u * t;     resRank = r - excl; }
        else               { resBin = 2u * t + 1; resRank = r - excl - c0; }
    }
    __syncthreads();
    const unsigned b1 = resBin, r2 = resRank;
    // sums over mid-bins strictly below b1
    {
        float    s = 0.f; unsigned c = 0u;
        if (2u * t     < b1) { s += sumS[2 * t];     c += cntS[2 * t]; }
        if (2u * t + 1 < b1) { s += sumS[2 * t + 1]; c += cntS[2 * t + 1]; }
        atomicAdd(&accS, s); atomicAdd(&accC, c);
    }
    __syncthreads();
    const float    sumBelow1 = accS;
    const unsigned cntBelow1 = accC;
    __syncthreads();

    // ---- round 2: low 10 bits within (b0, b1) ----
    cntS[t] = 0u; sumS[t] = 0.f;
    if (t == 0) { resBin = 0u; accS = 0.f; accC = 0u; }
    __syncthreads();
    for (unsigned i = t; i < M; i += 1024) {
        unsigned b = g_buf[i];
        if (((b >> 10) & 0x7FFu) == b1) {
            unsigned low = b & 0x3FFu;
            atomicAdd(&cntS[low], 1u);
            atomicAdd(&sumS[low], -__logf(__uint_as_float(b)));
        }
    }
    __syncthreads();
    local = cntS[t];
    scanS[t] = local;
    __syncthreads();
    for (int off = 1; off < 1024; off <<= 1) {
        unsigned add = (t >= off) ? scanS[t - off] : 0u;
        __syncthreads();
        scanS[t] += add;
        __syncthreads();
    }
    incl = scanS[t]; excl = incl - local;
    if (r2 >= excl && r2 < incl) resBin = (unsigned)t;
    __syncthreads();
    const unsigned b2 = resBin;
    // kept within bin b0: mid < b1, plus mid==b1 with low <= b2 (ties at kth all kept)
    {
        float    s = 0.f; unsigned c = 0u;
        if ((unsigned)t <= b2) { s = sumS[t]; c = cntS[t]; }
        atomicAdd(&accS, s); atomicAdd(&accC, c);
    }
    __syncthreads();

    if (t == 0) {
        float    sumBound = sumBelow1 + accS;
        unsigned cntBound = cntBelow1 + accC;
        unsigned kth_bits = (b0 << 21) | (b1 << 10) | b2;
        double   num; unsigned cnt;
        if (keep_all)                      { num = g_sumAll;                  cnt = g_cntAll; }
        else if (kth_bits <= B09_BITS)     { num = g_sumB;                    cnt = g_cntB;   }   // threshold = 0.9f
        else                               { num = g_sumL + (double)sumBound; cnt = g_cntL + cntBound; } // threshold = kth prob
        unsigned denom = (cnt > 0u) ? cnt : 1u;
        out[0] = (float)(num / (double)denom);
    }
}

// ---------------- launch ----------------
extern "C" void kernel_launch(void* const* d_in, const int* in_sizes, int n_in,
                              void* d_out, int out_size) {
    const float* pred = (const float*)d_in[0];
    const int*   tgt  = (const int*)d_in[1];
    float*       out  = (float*)d_out;

    zero_kernel<<<1, 1024>>>();
    compute_kernel<<<CB_BLOCKS, CB_THREADS>>>(pred, tgt);
    selA_kernel<<<1, 1024>>>();
    pass2_kernel<<<P2_BLOCKS, P2_THREADS>>>();
    finalize_kernel<<<1, 1024>>>(out);
}

// round 4
// speedup vs baseline: 1.1235x; 1.1235x over previous
#include <cuda_runtime.h>

// ---------------- problem constants (fixed shapes) ----------------
#define C_CLASSES   12
#define LOG_DHW     20                    // d*h*w = 64*128*128 = 2^20
#define DHW         (1u << LOG_DHW)
#define NPIX        (2u * DHW)            // 2,097,152
#define NPIX4       (NPIX / 4u)           // 524,288 uint4
#define MIN_KEPT_K  10000u
#define IGNORE_LBL  255
#define INF_BITS    0x7F800000u
#define B09_BITS    0x3F666666u           // bits of 0.9f (probs >= 0: uint order == float order)

#define GRID_BLOCKS   296                 // 2 per SM, guaranteed co-resident
#define BLOCK_THREADS 256

// ---------------- device scratch ----------------
__device__ unsigned int g_prob_bits[NPIX];   // prob-at-label bits; INF for invalid
__device__ unsigned int g_buf[NPIX];         // compacted elements of L0 bin b0
__device__ unsigned int g_hist[1024];        // L0 histogram of bits>>21
__device__ unsigned int g_bufcnt;
__device__ double       g_sumAll, g_sumB, g_sumL;
__device__ unsigned int g_cntAll, g_cntB, g_cntL;
__device__ unsigned int g_bar_count;         // software grid barrier (self-resetting)
__device__ unsigned int g_bar_gen;

// ---------------- software grid barrier ----------------
__device__ __forceinline__ void grid_barrier() {
    __syncthreads();
    __threadfence();                                  // release: my block's stores
    if (threadIdx.x == 0) {
        unsigned gen = *(volatile unsigned*)&g_bar_gen;
        unsigned a   = atomicAdd(&g_bar_count, 1u);
        if (a == GRID_BLOCKS - 1u) {
            *(volatile unsigned*)&g_bar_count = 0u;
            __threadfence();
            atomicAdd(&g_bar_gen, 1u);
        } else {
            while (*(volatile unsigned*)&g_bar_gen == gen) { }
        }
        __threadfence();                              // acquire
    }
    __syncthreads();
}

// ---------------- per-pixel CE -> prob bits ----------------
__device__ __forceinline__ unsigned int pixel_prob_bits(const float v[C_CLASSES], int l) {
    float m = v[0];
#pragma unroll
    for (int c = 1; c < C_CLASSES; c++) m = fmaxf(m, v[c]);
    float sum = 0.f, xl = 0.f;
#pragma unroll
    for (int c = 0; c < C_CLASSES; c++) {
        sum += __expf(v[c] - m);
        if (c == l) xl = v[c];
    }
    float lp = xl - (m + __logf(sum));
    if (l == IGNORE_LBL) return INF_BITS;      // invalid -> +inf (sorts last, like reference)
    return __float_as_uint(__expf(lp));        // prob in [0,1]
}

// ---------------- shared memory layout ----------------
// [0:64)            header: H[0]=b0 H[1]=r H[2]=keep_all H[3]=resBin H[4]=resRank
//                           H[5]=accC HF[6]=accS HF[7]=sumBelow1 H[8]=cntBelow1
// [64:64+8192)      phase1 hist (1024 u32) / finalize cnt (2048 u32) / reduce arrays
// [8256:16448)      finalize sum (2048 f32)
// [16448:17472)     scan (256 u32)
#define SMEM_BYTES 17472

__global__ void __launch_bounds__(BLOCK_THREADS, 2)
ohem_kernel(const float* __restrict__ pred, const int* __restrict__ tgt,
            float* __restrict__ out) {
    __shared__ __align__(16) unsigned char S[SMEM_BYTES];
    unsigned* H  = (unsigned*)S;
    float*    HF = (float*)S;
    const int t   = threadIdx.x;
    const int bid = blockIdx.x;

    // ================= phase 0: zero globals (block 0) =================
    if (bid == 0) {
        for (int i = t; i < 1024; i += BLOCK_THREADS) g_hist[i] = 0u;
        if (t == 0) {
            g_bufcnt = 0u;
            g_sumAll = 0.0; g_sumB = 0.0; g_sumL = 0.0;
            g_cntAll = 0u;  g_cntB = 0u;  g_cntL = 0u;
        }
    }
    grid_barrier();

    // ================= phase 1: prob bits + L0 histogram =================
    {
        unsigned* sh = (unsigned*)(S + 64);
        for (int i = t; i < 1024; i += BLOCK_THREADS) sh[i] = 0u;
        __syncthreads();

        const unsigned stride_px = GRID_BLOCKS * BLOCK_THREADS * 4u;
        for (unsigned p = (bid * BLOCK_THREADS + t) * 4u; p < NPIX; p += stride_px) {
            unsigned n = p >> LOG_DHW;
            unsigned s = p & (DHW - 1u);
            const float* base = pred + (((size_t)n * C_CLASSES) << LOG_DHW) + s;

            float4 x[C_CLASSES];
#pragma unroll
            for (int c = 0; c < C_CLASSES; c++)
                x[c] = __ldcs((const float4*)(base + ((size_t)c << LOG_DHW)));

            int4 lab = __ldcs((const int4*)tgt + (p >> 2));   // target is int32

            float v[C_CLASSES];
            uint4 pb;
#pragma unroll
            for (int c = 0; c < C_CLASSES; c++) v[c] = x[c].x;
            pb.x = pixel_prob_bits(v, lab.x);
#pragma unroll
            for (int c = 0; c < C_CLASSES; c++) v[c] = x[c].y;
            pb.y = pixel_prob_bits(v, lab.y);
#pragma unroll
            for (int c = 0; c < C_CLASSES; c++) v[c] = x[c].z;
            pb.z = pixel_prob_bits(v, lab.z);
#pragma unroll
            for (int c = 0; c < C_CLASSES; c++) v[c] = x[c].w;
            pb.w = pixel_prob_bits(v, lab.w);

            ((uint4*)g_prob_bits)[p >> 2] = pb;

            atomicAdd(&sh[pb.x >> 21], 1u);
            atomicAdd(&sh[pb.y >> 21], 1u);
            atomicAdd(&sh[pb.z >> 21], 1u);
            atomicAdd(&sh[pb.w >> 21], 1u);
        }
        __syncthreads();
        for (int i = t; i < 1024; i += BLOCK_THREADS) {
            unsigned c = sh[i];
            if (c) atomicAdd(&g_hist[i], c);
        }
    }
    grid_barrier();

    // ================= phase 2: every block locates kth L0 bin (L2 hits) =================
    {
        unsigned* scanS = (unsigned*)(S + 16448);
        unsigned inv       = g_hist[1020];                 // INF_BITS>>21 = 1020
        unsigned num_valid = NPIX - inv;
        unsigned keep_all  = (MIN_KEPT_K >= num_valid) ? 1u : 0u;
        unsigned mk        = (MIN_KEPT_K < num_valid) ? MIN_KEPT_K : num_valid;
        unsigned k         = (mk > 0u) ? (mk - 1u) : 0u;

        unsigned h[4], local = 0u;
#pragma unroll
        for (int i = 0; i < 4; i++) { h[i] = g_hist[t * 4 + i]; local += h[i]; }
        scanS[t] = local;
        __syncthreads();
        for (int off = 1; off < BLOCK_THREADS; off <<= 1) {
            unsigned add = (t >= off) ? scanS[t - off] : 0u;
            __syncthreads();
            scanS[t] += add;
            __syncthreads();
        }
        unsigned incl = scanS[t], excl = incl - local;
        if (k >= excl && k < incl) {
            unsigned run = excl;
            bool found = false;
#pragma unroll
            for (int i = 0; i < 4; i++) {
                if (!found) {
                    if (k < run + h[i]) { H[0] = t * 4 + i; H[1] = k - run; found = true; }
                    else run += h[i];
                }
            }
        }
        if (t == 0) H[2] = keep_all;
        __syncthreads();
    }

    // ================= phase 3: fused partial sums + boundary compaction =================
    {
        const unsigned b0 = H[0];
        float    sAll = 0.f, sB = 0.f, sL = 0.f;
        unsigned cAll = 0u,  cB = 0u,  cL = 0u;

        for (unsigned i = bid * BLOCK_THREADS + t; i < NPIX4; i += GRID_BLOCKS * BLOCK_THREADS) {
            uint4 pb = ((const uint4*)g_prob_bits)[i];
            unsigned bs[4] = { pb.x, pb.y, pb.z, pb.w };
#pragma unroll
            for (int j = 0; j < 4; j++) {
                unsigned b = bs[j];
                if (b != INF_BITS) {
                    float nll = -__logf(__uint_as_float(b));
                    cAll++; sAll += nll;
                    if (b <= B09_BITS) { cB++; sB += nll; }
                    unsigned bin = b >> 21;
                    if (bin < b0)       { cL++; sL += nll; }
                    else if (bin == b0) { g_buf[atomicAdd(&g_bufcnt, 1u)] = b; }
                }
            }
        }

#pragma unroll
        for (int off = 16; off > 0; off >>= 1) {
            sAll += __shfl_down_sync(0xFFFFFFFFu, sAll, off);
            sB   += __shfl_down_sync(0xFFFFFFFFu, sB,   off);
            sL   += __shfl_down_sync(0xFFFFFFFFu, sL,   off);
            cAll += __shfl_down_sync(0xFFFFFFFFu, cAll, off);
            cB   += __shfl_down_sync(0xFFFFFFFFu, cB,   off);
            cL   += __shfl_down_sync(0xFFFFFFFFu, cL,   off);
        }
        float*    ws = (float*)(S + 64);        // 3*8 floats
        unsigned* wc = (unsigned*)(S + 64 + 96);
        int w = t >> 5;
        if ((t & 31) == 0) {
            ws[w] = sAll; ws[8 + w] = sB; ws[16 + w] = sL;
            wc[w] = cAll; wc[8 + w] = cB; wc[16 + w] = cL;
        }
        __syncthreads();
        if (t == 0) {
            float    SA = 0.f, SBs = 0.f, SL = 0.f;
            unsigned CA = 0u,  CBc = 0u, CL = 0u;
#pragma unroll
            for (int i = 0; i < 8; i++) {
                SA += ws[i]; SBs += ws[8 + i]; SL += ws[16 + i];
                CA += wc[i]; CBc += wc[8 + i]; CL += wc[16 + i];
            }
            atomicAdd(&g_sumAll, (double)SA);
            atomicAdd(&g_sumB,   (double)SBs);
            atomicAdd(&g_sumL,   (double)SL);
            atomicAdd(&g_cntAll, CA);
            atomicAdd(&g_cntB,   CBc);
            atomicAdd(&g_cntL,   CL);
        }
    }
    grid_barrier();

    // ================= phase 4: finalize (block 0 only) =================
    if (bid != 0) return;
    {
        unsigned* cnt   = (unsigned*)(S + 64);        // 2048
        float*    sum   = (float*)(S + 64 + 8192);    // 2048
        unsigned* scanS = (unsigned*)(S + 16448);     // 256
        const unsigned keep_all = H[2];
        const unsigned b0 = H[0];
        const unsigned r  = H[1];
        const unsigned M  = g_bufcnt;

        // ---- round 1: mid 11 bits ----
        for (int i = t; i < 2048; i += BLOCK_THREADS) { cnt[i] = 0u; sum[i] = 0.f; }
        if (t == 0) { H[3] = 0u; H[4] = 0u; H[5] = 0u; HF[6] = 0.f; }
        __syncthreads();
        for (unsigned i = t; i < M; i += BLOCK_THREADS) {
            unsigned b = g_buf[i];
            unsigned mid = (b >> 10) & 0x7FFu;
            atomicAdd(&cnt[mid], 1u);
            atomicAdd(&sum[mid], -__logf(__uint_as_float(b)));
        }
        __syncthreads();
        {
            unsigned h[8], local = 0u;
#pragma unroll
            for (int j = 0; j < 8; j++) { h[j] = cnt[t * 8 + j]; local += h[j]; }
            scanS[t] = local;
            __syncthreads();
            for (int off = 1; off < BLOCK_THREADS; off <<= 1) {
                unsigned add = (t >= off) ? scanS[t - off] : 0u;
                __syncthreads();
                scanS[t] += add;
                __syncthreads();
            }
            unsigned incl = scanS[t], excl = incl - local;
            if (r >= excl && r < incl) {
                unsigned run = excl;
                bool found = false;
#pragma unroll
                for (int j = 0; j < 8; j++) {
                    if (!found) {
                        if (r < run + h[j]) { H[3] = t * 8 + j; H[4] = r - run; found = true; }
                        else run += h[j];
                    }
                }
            }
            __syncthreads();
            unsigned b1 = H[3];
            float    s = 0.f; unsigned c = 0u;
#pragma unroll
            for (int j = 0; j < 8; j++)
                if ((unsigned)(t * 8 + j) < b1) { s += sum[t * 8 + j]; c += h[j]; }
            atomicAdd(&HF[6], s); atomicAdd(&H[5], c);
            __syncthreads();
            if (t == 0) { HF[7] = HF[6]; H[8] = H[5]; }   // sumBelow1 / cntBelow1
            __syncthreads();
        }
        const unsigned b1 = H[3], r2 = H[4];

        // ---- round 2: low 10 bits within (b0, b1) ----
        for (int i = t; i < 1024; i += BLOCK_THREADS) { cnt[i] = 0u; sum[i] = 0.f; }
        if (t == 0) { H[3] = 0u; H[5] = 0u; HF[6] = 0.f; }
        __syncthreads();
        for (unsigned i = t; i < M; i += BLOCK_THREADS) {
            unsigned b = g_buf[i];
            if (((b >> 10) & 0x7FFu) == b1) {
                unsigned low = b & 0x3FFu;
                atomicAdd(&cnt[low], 1u);
                atomicAdd(&sum[low], -__logf(__uint_as_float(b)));
            }
        }
        __syncthreads();
        {
            unsigned h[4], local = 0u;
#pragma unroll
            for (int j = 0; j < 4; j++) { h[j] = cnt[t * 4 + j]; local += h[j]; }
            scanS[t] = local;
            __syncthreads();
            for (int off = 1; off < BLOCK_THREADS; off <<= 1) {
                unsigned add = (t >= off) ? scanS[t - off] : 0u;
                __syncthreads();
                scanS[t] += add;
                __syncthreads();
            }
            unsigned incl = scanS[t], excl = incl - local;
            if (r2 >= excl && r2 < incl) {
                unsigned run = excl;
                bool found = false;
#pragma unroll
                for (int j = 0; j < 4; j++) {
                    if (!found) {
                        if (r2 < run + h[j]) { H[3] = t * 4 + j; found = true; }
                        else run += h[j];
                    }
                }
            }
            __syncthreads();
            unsigned b2 = H[3];
            float    s = 0.f; unsigned c = 0u;
#pragma unroll
            for (int j = 0; j < 4; j++)
                if ((unsigned)(t * 4 + j) <= b2) { s += sum[t * 4 + j]; c += h[j]; }   // ties kept
            atomicAdd(&HF[6], s); atomicAdd(&H[5], c);
            __syncthreads();

            if (t == 0) {
                float    sumBound = HF[7] + HF[6];
                unsigned cntBound = H[8] + H[5];
                unsigned kth_bits = (b0 << 21) | (b1 << 10) | b2;
                double   num; unsigned cntk;
                if (keep_all)                  { num = g_sumAll;                  cntk = g_cntAll; }
                else if (kth_bits <= B09_BITS) { num = g_sumB;                    cntk = g_cntB;   }  // threshold = 0.9
                else                           { num = g_sumL + (double)sumBound; cntk = g_cntL + cntBound; }
                unsigned denom = (cntk > 0u) ? cntk : 1u;
                out[0] = (float)(num / (double)denom);
            }
        }
    }
}

// ---------------- launch ----------------
extern "C" void kernel_launch(void* const* d_in, const int* in_sizes, int n_in,
                              void* d_out, int out_size) {
    const float* pred = (const float*)d_in[0];
    const int*   tgt  = (const int*)d_in[1];
    float*       out  = (float*)d_out;
    ohem_kernel<<<GRID_BLOCKS, BLOCK_THREADS>>>(pred, tgt, out);
}